// round 17
// baseline (speedup 1.0000x reference)
#include <cuda_runtime.h>
#include <math.h>
#include <stdint.h>

// Problem constants
#define Dm   1024
#define Sm   2048
#define Bm   2
#define Hh   16
#define DHh  64
#define ROWS (Bm*Sm)      // 4096
#define NEGM (-1e9f)

// ---------------------------------------------------------------------------
// Scratch (module-load-time allocation; no runtime alloc)
// ---------------------------------------------------------------------------
__device__ float g_xln [ROWS*Dm];
__device__ float g_xlnr[ROWS*Dm];
__device__ float g_q   [ROWS*Dm];
__device__ float g_k   [ROWS*Dm];
__device__ float g_v   [ROWS*Dm];
__device__ float g_ctx [ROWS*Dm];
__device__ float g_h   [ROWS*Dm];
__device__ float g_hln [ROWS*Dm];
__device__ float g_r   [ROWS*Dm];
__device__ float g_zr  [ROWS*Dm];
__device__ float g_mlp [ROWS*4*Dm];

__device__ __forceinline__ float gelu_f(float x) {
    return 0.5f * x * (1.0f + erff(x * 0.70710678118654752440f));
}

// TF32 input rounding — same conversion cuBLAS/CUTLASS apply for f32 matmuls.
__device__ __forceinline__ float tf32r(float x) {
    float r;
    asm("cvt.rna.tf32.f32 %0, %1;" : "=f"(r) : "f"(x));
    return r;
}

// ---------------------------------------------------------------------------
// LayerNorm over D=1024: one block per row, 256 threads, ONE float4 per thread.
// x stays in registers (no smem staging). Optionally writes full and/or
// tf32-rounded outputs.
// ---------------------------------------------------------------------------
template<bool WF, bool WR>
__global__ void __launch_bounds__(256)
ln_kernel(const float* __restrict__ in, const float* __restrict__ g,
          const float* __restrict__ bb, float* __restrict__ out,
          float* __restrict__ out_r)
{
    __shared__ float red[8];
    int row = blockIdx.x, tid = threadIdx.x;

    float4 xv = ((const float4*)(in + (size_t)row * Dm))[tid];

    float s = xv.x + xv.y + xv.z + xv.w;
    #pragma unroll
    for (int o = 16; o > 0; o >>= 1) s += __shfl_xor_sync(0xffffffffu, s, o);
    if ((tid & 31) == 0) red[tid >> 5] = s;
    __syncthreads();
    float tot = 0.f;
    #pragma unroll
    for (int i = 0; i < 8; i++) tot += red[i];
    float mu = tot * (1.0f / Dm);

    float dx = xv.x - mu, dy = xv.y - mu, dz = xv.z - mu, dw = xv.w - mu;
    float vs = dx*dx + dy*dy + dz*dz + dw*dw;
    #pragma unroll
    for (int o = 16; o > 0; o >>= 1) vs += __shfl_xor_sync(0xffffffffu, vs, o);
    __syncthreads();
    if ((tid & 31) == 0) red[tid >> 5] = vs;
    __syncthreads();
    tot = 0.f;
    #pragma unroll
    for (int i = 0; i < 8; i++) tot += red[i];
    float inv = rsqrtf(tot * (1.0f / Dm) + 1e-5f);

    float4 gv = ((const float4*)g)[tid];
    float4 bv = ((const float4*)bb)[tid];
    float4 y;
    y.x = dx * inv * gv.x + bv.x;
    y.y = dy * inv * gv.y + bv.y;
    y.z = dz * inv * gv.z + bv.z;
    y.w = dw * inv * gv.w + bv.w;

    if (WF) ((float4*)(out + (size_t)row * Dm))[tid] = y;
    if (WR) ((float4*)(out_r + (size_t)row * Dm))[tid] =
        make_float4(tf32r(y.x), tf32r(y.y), tf32r(y.z), tf32r(y.w));
}

// Embedding gather (tok_emb[ids] + pos_emb) fused with LayerNorm, dual output
__global__ void __launch_bounds__(256)
embed_ln_kernel(const int* __restrict__ ids, const float* __restrict__ tok,
                const float* __restrict__ pos, const float* __restrict__ g,
                const float* __restrict__ bb, float* __restrict__ out,
                float* __restrict__ out_r)
{
    __shared__ float red[8];
    int row = blockIdx.x, tid = threadIdx.x;
    int spos = row % Sm;
    int id = ids[row];

    float4 tv = ((const float4*)(tok + (size_t)id * Dm))[tid];
    float4 pv = ((const float4*)(pos + (size_t)spos * Dm))[tid];
    float4 xv = make_float4(tv.x + pv.x, tv.y + pv.y, tv.z + pv.z, tv.w + pv.w);

    float s = xv.x + xv.y + xv.z + xv.w;
    #pragma unroll
    for (int o = 16; o > 0; o >>= 1) s += __shfl_xor_sync(0xffffffffu, s, o);
    if ((tid & 31) == 0) red[tid >> 5] = s;
    __syncthreads();
    float tot = 0.f;
    #pragma unroll
    for (int i = 0; i < 8; i++) tot += red[i];
    float mu = tot * (1.0f / Dm);

    float dx = xv.x - mu, dy = xv.y - mu, dz = xv.z - mu, dw = xv.w - mu;
    float vs = dx*dx + dy*dy + dz*dz + dw*dw;
    #pragma unroll
    for (int o = 16; o > 0; o >>= 1) vs += __shfl_xor_sync(0xffffffffu, vs, o);
    __syncthreads();
    if ((tid & 31) == 0) red[tid >> 5] = vs;
    __syncthreads();
    tot = 0.f;
    #pragma unroll
    for (int i = 0; i < 8; i++) tot += red[i];
    float inv = rsqrtf(tot * (1.0f / Dm) + 1e-5f);

    float4 gv = ((const float4*)g)[tid];
    float4 bv = ((const float4*)bb)[tid];
    float4 y;
    y.x = dx * inv * gv.x + bv.x;
    y.y = dy * inv * gv.y + bv.y;
    y.z = dz * inv * gv.z + bv.z;
    y.w = dw * inv * gv.w + bv.w;

    ((float4*)(out + (size_t)row * Dm))[tid] = y;
    ((float4*)(out_r + (size_t)row * Dm))[tid] =
        make_float4(tf32r(y.x), tf32r(y.y), tf32r(y.z), tf32r(y.w));
}

// ---------------------------------------------------------------------------
// mma.sync m16n8k8 tf32 helper
// ---------------------------------------------------------------------------
__device__ __forceinline__ void mma_tf32(float* c, uint32_t a0, uint32_t a1,
                                         uint32_t a2, uint32_t a3,
                                         uint32_t b0, uint32_t b1)
{
    asm volatile(
        "mma.sync.aligned.m16n8k8.row.col.f32.tf32.tf32.f32 "
        "{%0,%1,%2,%3}, {%4,%5,%6,%7}, {%8,%9}, {%0,%1,%2,%3};"
        : "+f"(c[0]), "+f"(c[1]), "+f"(c[2]), "+f"(c[3])
        : "r"(a0), "r"(a1), "r"(a2), "r"(a3), "r"(b0), "r"(b1));
}

// ---------------------------------------------------------------------------
// Tensor-core GEMM, 2-stage cp.async pipeline, rounding at fragment load:
// B (weights) always tf32-rounded at fragment load; A rounded iff CVTA
// (otherwise A was pre-rounded by its producer). Bit-identical to pre-rounding.
// C = A @ W + bias (+residual) (+GELU, stored tf32-rounded).
// ---------------------------------------------------------------------------
#define ASTR 40
#define BSTR 136
#define SA (128*ASTR)
#define SB (32*BSTR)
#define GEMM_SMEM (2*(SA+SB)*4)

extern __shared__ float smem_dyn[];

template<bool RES, bool GELU, bool CVTA>
__global__ void __launch_bounds__(256, 2)
gemm_tc(const float* __restrict__ A, const float* __restrict__ W,
        const float* __restrict__ bias, const float* __restrict__ Rsrc,
        float* __restrict__ C, int M, int N, int K)
{
    float* As = smem_dyn;
    float* Bs = smem_dyn + 2*SA;

    int tid = threadIdx.x, lane = tid & 31, warp = tid >> 5;
    int wm = warp >> 2, wn = warp & 3;
    int bm = blockIdx.y * 128, bn = blockIdx.x * 128;
    int g = lane >> 2, t4 = lane & 3;
    int swz = (g & 4);
    int ntiles = K >> 5;

    auto issue = [&](int tile, int st) {
        int k0 = tile * 32;
        float* Ad = As + st * SA;
        float* Bd = Bs + st * SB;
        #pragma unroll
        for (int it = 0; it < 4; it++) {
            int idx = tid + it * 256;
            int r = idx >> 3, c = (idx & 7) << 2;
            uint32_t d = (uint32_t)__cvta_generic_to_shared(Ad + r * ASTR + (c ^ (r & 4)));
            const float* s = A + (size_t)(bm + r) * K + k0 + c;
            asm volatile("cp.async.cg.shared.global [%0], [%1], 16;" :: "r"(d), "l"(s));
        }
        #pragma unroll
        for (int it = 0; it < 4; it++) {
            int idx = tid + it * 256;
            int r = idx >> 5, c = (idx & 31) << 2;
            uint32_t d = (uint32_t)__cvta_generic_to_shared(Bd + r * BSTR + c);
            const float* s = W + (size_t)(k0 + r) * N + bn + c;
            asm volatile("cp.async.cg.shared.global [%0], [%1], 16;" :: "r"(d), "l"(s));
        }
    };

    float acc[4][4][4];
    #pragma unroll
    for (int i = 0; i < 4; i++)
        #pragma unroll
        for (int j = 0; j < 4; j++)
            #pragma unroll
            for (int c = 0; c < 4; c++) acc[i][j][c] = 0.f;

    issue(0, 0);
    asm volatile("cp.async.commit_group;");

    for (int t = 0; t < ntiles; t++) {
        if (t + 1 < ntiles) {
            issue(t + 1, (t + 1) & 1);
            asm volatile("cp.async.commit_group;");
            asm volatile("cp.async.wait_group 1;");
        } else {
            asm volatile("cp.async.wait_group 0;");
        }
        __syncthreads();

        const float* Ast = As + (t & 1) * SA;
        const float* Bst = Bs + (t & 1) * SB;

        #pragma unroll
        for (int ks = 0; ks < 4; ks++) {
            int kb = ks * 8;
            int kA  = (kb + t4) ^ swz;
            int kA4 = (kb + t4 + 4) ^ swz;
            uint32_t a[4][4], b[4][2];
            #pragma unroll
            for (int mt = 0; mt < 4; mt++) {
                int r0 = wm * 64 + mt * 16 + g;
                int r1 = r0 + 8;
                float a0 = Ast[r0 * ASTR + kA ];
                float a1 = Ast[r1 * ASTR + kA ];
                float a2 = Ast[r0 * ASTR + kA4];
                float a3 = Ast[r1 * ASTR + kA4];
                if (CVTA) { a0 = tf32r(a0); a1 = tf32r(a1); a2 = tf32r(a2); a3 = tf32r(a3); }
                a[mt][0] = __float_as_uint(a0);
                a[mt][1] = __float_as_uint(a1);
                a[mt][2] = __float_as_uint(a2);
                a[mt][3] = __float_as_uint(a3);
            }
            #pragma unroll
            for (int nt = 0; nt < 4; nt++) {
                int col = wn * 32 + nt * 8 + g;
                b[nt][0] = __float_as_uint(tf32r(Bst[(kb + t4    ) * BSTR + col]));
                b[nt][1] = __float_as_uint(tf32r(Bst[(kb + t4 + 4) * BSTR + col]));
            }
            #pragma unroll
            for (int mt = 0; mt < 4; mt++)
                #pragma unroll
                for (int nt = 0; nt < 4; nt++)
                    mma_tf32(acc[mt][nt], a[mt][0], a[mt][1], a[mt][2], a[mt][3],
                             b[nt][0], b[nt][1]);
        }
        __syncthreads();
    }

    #pragma unroll
    for (int mt = 0; mt < 4; mt++) {
        #pragma unroll
        for (int nt = 0; nt < 4; nt++) {
            int col = bn + wn * 32 + nt * 8 + t4 * 2;
            float b0 = bias[col], b1 = bias[col + 1];
            #pragma unroll
            for (int half = 0; half < 2; half++) {
                int row = bm + wm * 64 + mt * 16 + g + half * 8;
                float v0 = acc[mt][nt][half * 2 + 0] + b0;
                float v1 = acc[mt][nt][half * 2 + 1] + b1;
                if (RES) {
                    v0 += Rsrc[(size_t)row * N + col];
                    v1 += Rsrc[(size_t)row * N + col + 1];
                }
                if (GELU) {
                    // GELU output feeds the next GEMM's A input only -> store rounded
                    v0 = tf32r(gelu_f(v0)); v1 = tf32r(gelu_f(v1));
                }
                *(float2*)(C + (size_t)row * N + col) = make_float2(v0, v1);
            }
        }
    }
}

// ---------------------------------------------------------------------------
// Tensor-core flash attention; ctx stored tf32-rounded (feeds GEMM A input).
// ---------------------------------------------------------------------------
#define KSTR 68
#define VSTR 72
#define PSTR 36

template<bool CAUSAL>
__global__ void __launch_bounds__(128)
attn_tc(const float* __restrict__ Qp, const float* __restrict__ Kp,
        const float* __restrict__ Vp, const int* __restrict__ ids,
        float* __restrict__ O)
{
    __shared__ float Qs[64 * KSTR];
    __shared__ float Ks[32 * KSTR];
    __shared__ float Vs[32 * VSTR];
    __shared__ float Ps[64 * PSTR];
    __shared__ int   ids_s[32];

    int b = blockIdx.z, h = blockIdx.y, qb = blockIdx.x;
    int tid = threadIdx.x, lane = tid & 31, warp = tid >> 5;
    int g = lane >> 2, t4 = lane & 3;

    #pragma unroll
    for (int i = tid; i < 64 * 16; i += 128) {
        int r = i >> 4, c4 = (i & 15) << 2;
        size_t base = (((size_t)b * Sm + qb * 64 + r) * Hh + h) * DHh + c4;
        float4 v = *(const float4*)(Qp + base);
        Qs[r*KSTR + c4+0] = tf32r(v.x) * 0.125f;
        Qs[r*KSTR + c4+1] = tf32r(v.y) * 0.125f;
        Qs[r*KSTR + c4+2] = tf32r(v.z) * 0.125f;
        Qs[r*KSTR + c4+3] = tf32r(v.w) * 0.125f;
    }
    __syncthreads();

    uint32_t qa[8][4];
    int rw0 = warp * 16 + g, rw1 = rw0 + 8;
    #pragma unroll
    for (int kc = 0; kc < 8; kc++) {
        qa[kc][0] = __float_as_uint(Qs[rw0*KSTR + kc*8 + t4    ]);
        qa[kc][1] = __float_as_uint(Qs[rw1*KSTR + kc*8 + t4    ]);
        qa[kc][2] = __float_as_uint(Qs[rw0*KSTR + kc*8 + t4 + 4]);
        qa[kc][3] = __float_as_uint(Qs[rw1*KSTR + kc*8 + t4 + 4]);
    }

    float m0 = -1e30f, m1 = -1e30f, l0 = 0.f, l1 = 0.f;
    float o[8][4];
    #pragma unroll
    for (int nt = 0; nt < 8; nt++)
        #pragma unroll
        for (int c = 0; c < 4; c++) o[nt][c] = 0.f;

    int qrow0 = qb * 64 + warp * 16 + g;
    int qrow1 = qrow0 + 8;
    int ktiles = CAUSAL ? (qb * 2 + 2) : (Sm / 32);

    for (int kt = 0; kt < ktiles; kt++) {
        int k0 = kt * 32;
        __syncthreads();
        #pragma unroll
        for (int i = tid; i < 32 * 16; i += 128) {
            int r = i >> 4, c4 = (i & 15) << 2;
            size_t base = (((size_t)b * Sm + k0 + r) * Hh + h) * DHh + c4;
            float4 vk = *(const float4*)(Kp + base);
            Ks[r*KSTR + c4+0] = tf32r(vk.x); Ks[r*KSTR + c4+1] = tf32r(vk.y);
            Ks[r*KSTR + c4+2] = tf32r(vk.z); Ks[r*KSTR + c4+3] = tf32r(vk.w);
            float4 vv = *(const float4*)(Vp + base);
            Vs[r*VSTR + c4+0] = tf32r(vv.x); Vs[r*VSTR + c4+1] = tf32r(vv.y);
            Vs[r*VSTR + c4+2] = tf32r(vv.z); Vs[r*VSTR + c4+3] = tf32r(vv.w);
        }
        if (tid < 32) ids_s[tid] = ids[b * Sm + k0 + tid];
        __syncthreads();

        float s[4][4];
        #pragma unroll
        for (int nt = 0; nt < 4; nt++) {
            s[nt][0] = s[nt][1] = s[nt][2] = s[nt][3] = 0.f;
            const float* kb = &Ks[(nt*8 + g) * KSTR];
            #pragma unroll
            for (int kc = 0; kc < 8; kc++) {
                uint32_t b0 = __float_as_uint(kb[kc*8 + t4    ]);
                uint32_t b1 = __float_as_uint(kb[kc*8 + t4 + 4]);
                mma_tf32(s[nt], qa[kc][0], qa[kc][1], qa[kc][2], qa[kc][3], b0, b1);
            }
        }

        bool diag = CAUSAL && (k0 + 31 > qb * 64);
        #pragma unroll
        for (int nt = 0; nt < 4; nt++) {
            int lk0 = nt*8 + 2*t4, lk1 = lk0 + 1;
            float pad0 = (ids_s[lk0] == 0) ? NEGM : 0.f;
            float pad1 = (ids_s[lk1] == 0) ? NEGM : 0.f;
            s[nt][0] += pad0; s[nt][1] += pad1;
            s[nt][2] += pad0; s[nt][3] += pad1;
            if (diag) {
                int key0 = k0 + lk0, key1 = k0 + lk1;
                if (key0 > qrow0) s[nt][0] += NEGM;
                if (key1 > qrow0) s[nt][1] += NEGM;
                if (key0 > qrow1) s[nt][2] += NEGM;
                if (key1 > qrow1) s[nt][3] += NEGM;
            }
        }

        float tm0 = -1e30f, tm1 = -1e30f;
        #pragma unroll
        for (int nt = 0; nt < 4; nt++) {
            tm0 = fmaxf(tm0, fmaxf(s[nt][0], s[nt][1]));
            tm1 = fmaxf(tm1, fmaxf(s[nt][2], s[nt][3]));
        }
        tm0 = fmaxf(tm0, __shfl_xor_sync(0xffffffffu, tm0, 1));
        tm0 = fmaxf(tm0, __shfl_xor_sync(0xffffffffu, tm0, 2));
        tm1 = fmaxf(tm1, __shfl_xor_sync(0xffffffffu, tm1, 1));
        tm1 = fmaxf(tm1, __shfl_xor_sync(0xffffffffu, tm1, 2));

        float mn0 = fmaxf(m0, tm0), mn1 = fmaxf(m1, tm1);
        float cr0 = expf(m0 - mn0), cr1 = expf(m1 - mn1);
        l0 *= cr0; l1 *= cr1;
        #pragma unroll
        for (int nt = 0; nt < 8; nt++) {
            o[nt][0] *= cr0; o[nt][1] *= cr0;
            o[nt][2] *= cr1; o[nt][3] *= cr1;
        }

        float ps0 = 0.f, ps1 = 0.f;
        #pragma unroll
        for (int nt = 0; nt < 4; nt++) {
            float p0 = expf(s[nt][0] - mn0);
            float p1 = expf(s[nt][1] - mn0);
            float p2 = expf(s[nt][2] - mn1);
            float p3 = expf(s[nt][3] - mn1);
            ps0 += p0 + p1; ps1 += p2 + p3;
            *(float2*)&Ps[rw0*PSTR + nt*8 + 2*t4] = make_float2(tf32r(p0), tf32r(p1));
            *(float2*)&Ps[rw1*PSTR + nt*8 + 2*t4] = make_float2(tf32r(p2), tf32r(p3));
        }
        ps0 += __shfl_xor_sync(0xffffffffu, ps0, 1);
        ps0 += __shfl_xor_sync(0xffffffffu, ps0, 2);
        ps1 += __shfl_xor_sync(0xffffffffu, ps1, 1);
        ps1 += __shfl_xor_sync(0xffffffffu, ps1, 2);
        l0 += ps0; l1 += ps1;
        m0 = mn0; m1 = mn1;
        __syncwarp();

        #pragma unroll
        for (int kc = 0; kc < 4; kc++) {
            uint32_t a0 = __float_as_uint(Ps[rw0*PSTR + kc*8 + t4    ]);
            uint32_t a1 = __float_as_uint(Ps[rw1*PSTR + kc*8 + t4    ]);
            uint32_t a2 = __float_as_uint(Ps[rw0*PSTR + kc*8 + t4 + 4]);
            uint32_t a3 = __float_as_uint(Ps[rw1*PSTR + kc*8 + t4 + 4]);
            const float* v0p = &Vs[(kc*8 + t4    ) * VSTR];
            const float* v1p = &Vs[(kc*8 + t4 + 4) * VSTR];
            #pragma unroll
            for (int nt = 0; nt < 8; nt++) {
                uint32_t b0 = __float_as_uint(v0p[nt*8 + g]);
                uint32_t b1 = __float_as_uint(v1p[nt*8 + g]);
                mma_tf32(o[nt], a0, a1, a2, a3, b0, b1);
            }
        }
    }

    float i0 = 1.0f / l0, i1 = 1.0f / l1;
    size_t ob0 = (((size_t)b * Sm + qrow0) * Hh + h) * DHh;
    size_t ob1 = (((size_t)b * Sm + qrow1) * Hh + h) * DHh;
    #pragma unroll
    for (int nt = 0; nt < 8; nt++) {
        int col = nt*8 + 2*t4;
        *(float2*)(O + ob0 + col) = make_float2(tf32r(o[nt][0] * i0), tf32r(o[nt][1] * i0));
        *(float2*)(O + ob1 + col) = make_float2(tf32r(o[nt][2] * i1), tf32r(o[nt][3] * i1));
    }
}

// ---------------------------------------------------------------------------
// Launch
// ---------------------------------------------------------------------------
extern "C" void kernel_launch(void* const* d_in, const int* in_sizes, int n_in,
                              void* d_out, int out_size)
{
    const float* input_embedding = (const float*)d_in[0];
    const int*   input_ids       = (const int*)  d_in[1];
    const int*   target_ids      = (const int*)  d_in[2];
    const float* tok_emb = (const float*)d_in[3];
    const float* pos_emb = (const float*)d_in[4];
    const float* ln1_g = (const float*)d_in[5],  *ln1_b = (const float*)d_in[6];
    const float* q1_w  = (const float*)d_in[7],  *q1_b  = (const float*)d_in[8];
    const float* k1_w  = (const float*)d_in[9],  *k1_b  = (const float*)d_in[10];
    const float* v1_w  = (const float*)d_in[11], *v1_b  = (const float*)d_in[12];
    const float* out1_w= (const float*)d_in[13], *out1_b= (const float*)d_in[14];
    const float* ln2_g = (const float*)d_in[15], *ln2_b = (const float*)d_in[16];
    const float* q2_w  = (const float*)d_in[17], *q2_b  = (const float*)d_in[18];
    const float* k2_w  = (const float*)d_in[19], *k2_b  = (const float*)d_in[20];
    const float* v2_w  = (const float*)d_in[21], *v2_b  = (const float*)d_in[22];
    const float* out2_w= (const float*)d_in[23], *out2_b= (const float*)d_in[24];
    const float* ln3_g = (const float*)d_in[25], *ln3_b = (const float*)d_in[26];
    const float* mlp_w1= (const float*)d_in[27], *mlp_b1= (const float*)d_in[28];
    const float* mlp_w2= (const float*)d_in[29], *mlp_b2= (const float*)d_in[30];
    float* out = (float*)d_out;

    float *xln,*xlnr,*q,*k,*v,*ctx,*h,*hln,*r,*zr,*mlp;
    cudaGetSymbolAddress((void**)&xln,  g_xln);
    cudaGetSymbolAddress((void**)&xlnr, g_xlnr);
    cudaGetSymbolAddress((void**)&q,    g_q);
    cudaGetSymbolAddress((void**)&k,    g_k);
    cudaGetSymbolAddress((void**)&v,    g_v);
    cudaGetSymbolAddress((void**)&ctx,  g_ctx);
    cudaGetSymbolAddress((void**)&h,    g_h);
    cudaGetSymbolAddress((void**)&hln,  g_hln);
    cudaGetSymbolAddress((void**)&r,    g_r);
    cudaGetSymbolAddress((void**)&zr,   g_zr);
    cudaGetSymbolAddress((void**)&mlp,  g_mlp);

    cudaFuncSetAttribute(gemm_tc<false,false,false>, cudaFuncAttributeMaxDynamicSharedMemorySize, GEMM_SMEM);
    cudaFuncSetAttribute(gemm_tc<false,false,true >, cudaFuncAttributeMaxDynamicSharedMemorySize, GEMM_SMEM);
    cudaFuncSetAttribute(gemm_tc<true ,false,false>, cudaFuncAttributeMaxDynamicSharedMemorySize, GEMM_SMEM);
    cudaFuncSetAttribute(gemm_tc<false,true ,false>, cudaFuncAttributeMaxDynamicSharedMemorySize, GEMM_SMEM);

    dim3 gP(Dm / 128, ROWS / 128);      // projections: N=1024
    dim3 gU(4 * Dm / 128, ROWS / 128);  // MLP up: N=4096
    dim3 gA(Sm / 64, Hh, Bm);           // attention: 64 q rows per block

    // x = LN1(tok_emb[target_ids] + pos_emb); xln full, xlnr rounded
    embed_ln_kernel<<<ROWS, 256>>>(target_ids, tok_emb, pos_emb, ln1_g, ln1_b, xln, xlnr);

    // Self-attention QKV (A pre-rounded; weights rounded at fragment load)
    gemm_tc<false,false,false><<<gP, 256, GEMM_SMEM>>>(xlnr, q1_w, q1_b, nullptr, q, ROWS, Dm, Dm);
    gemm_tc<false,false,false><<<gP, 256, GEMM_SMEM>>>(xlnr, k1_w, k1_b, nullptr, k, ROWS, Dm, Dm);
    gemm_tc<false,false,false><<<gP, 256, GEMM_SMEM>>>(xlnr, v1_w, v1_b, nullptr, v, ROWS, Dm, Dm);
    attn_tc<true><<<gA, 128>>>(q, k, v, target_ids, ctx);
    // h = xln + ctx @ out1_w + out1_b
    gemm_tc<true,false,false><<<gP, 256, GEMM_SMEM>>>(ctx, out1_w, out1_b, xln, h, ROWS, Dm, Dm);

    // Cross-attention. Reference reassigns h = LN2(h); residual is hln.
    ln_kernel<true,false><<<ROWS, 256>>>(h, ln2_g, ln2_b, hln, nullptr);
    gemm_tc<false,false,true ><<<gP, 256, GEMM_SMEM>>>(hln, q2_w, q2_b, nullptr, q, ROWS, Dm, Dm);
    gemm_tc<false,false,true ><<<gP, 256, GEMM_SMEM>>>(input_embedding, k2_w, k2_b, nullptr, k, ROWS, Dm, Dm);
    gemm_tc<false,false,true ><<<gP, 256, GEMM_SMEM>>>(input_embedding, v2_w, v2_b, nullptr, v, ROWS, Dm, Dm);
    attn_tc<false><<<gA, 128>>>(q, k, v, input_ids, ctx);
    // r = LN2(h) + ctx @ out2_w + out2_b
    gemm_tc<true,false,false><<<gP, 256, GEMM_SMEM>>>(ctx, out2_w, out2_b, hln, r, ROWS, Dm, Dm);

    // MLP (ln3 writes only the rounded output; GELU epilogue stores rounded)
    ln_kernel<false,true><<<ROWS, 256>>>(r, ln3_g, ln3_b, nullptr, zr);
    gemm_tc<false,true ,false><<<gU, 256, GEMM_SMEM>>>(zr, mlp_w1, mlp_b1, nullptr, mlp, ROWS, 4 * Dm, Dm);
    gemm_tc<true ,false,false><<<gP, 256, GEMM_SMEM>>>(mlp, mlp_w2, mlp_b2, r, out, ROWS, Dm, 4 * Dm);
}